// round 5
// baseline (speedup 1.0000x reference)
#include <cuda_runtime.h>
#include <cuda_bf16.h>
#include <math.h>

// ----------------------------------------------------------------------------
// GraphSAGE (3 layers) + up-proj + tri-pooling + MLP head. CSR-gather,
// 4-nodes-per-warp float4 aggregation. No float atomics.
// N=100000, E=1600000, G=256, H=32, UP=128, out 51.
// ----------------------------------------------------------------------------

#define MAXN 100000
#define MAXE 1600000
#define MAXG 256

__device__ int   g_csr[MAXE];          // src ids grouped by dst
__device__ int   g_src[MAXE];
__device__ int   g_dst[MAXE];
__device__ int   g_cnt[MAXN];
__device__ int   g_rowptr[MAXN + 1];
__device__ int   g_cursor[MAXN];
__device__ float g_h1[MAXN * 32];
__device__ float g_h2[MAXN * 32];
__device__ float g_h4[(size_t)MAXN * 128];
__device__ int   g_start[MAXG + 1];
__device__ float g_part[MAXG * 8 * 256];   // (graph, octant): [sum(128)|max(128)]
__device__ int   g_flags[2];               // [0]=edges int64, [1]=batch int64

__device__ __forceinline__ float lrelu(float v) { return v > 0.f ? v : 0.01f * v; }
__device__ __forceinline__ float4 lrelu4(float4 v) {
    return make_float4(lrelu(v.x), lrelu(v.y), lrelu(v.z), lrelu(v.w));
}

// ---------------------------------------------------------------------------
// Init: zero histogram + parallel dtype detect (warp0=edges, warp1=batch).
// ---------------------------------------------------------------------------
__global__ void k_init(const unsigned int* __restrict__ ew,
                       const unsigned int* __restrict__ bw, int bbase, int N) {
    int i = blockIdx.x * blockDim.x + threadIdx.x;
    if (i < N) g_cnt[i] = 0;
    if (blockIdx.x == 0 && threadIdx.x < 64) {
        int lane = threadIdx.x & 31;
        if (threadIdx.x < 32) {
            unsigned v = ew[2 * lane + 1];
            unsigned nz = __ballot_sync(0xffffffffu, v != 0u);
            if (lane == 0) g_flags[0] = (nz == 0u);
        } else {
            unsigned v = bw[bbase + 2 * lane + 1];
            unsigned nz = __ballot_sync(0xffffffffu, v != 0u);
            if (lane == 0) g_flags[1] = (nz == 0u);
        }
    }
}

// Convert edge index to int32 + in-degree histogram (int atomics).
__global__ void k_convert_hist(const void* __restrict__ eidx, int E) {
    int i = blockIdx.x * blockDim.x + threadIdx.x;
    if (i >= E) return;
    int s, d;
    if (g_flags[0]) {
        const long long* p = (const long long*)eidx;
        s = (int)p[i];
        d = (int)p[(size_t)E + i];
    } else {
        const int* p = (const int*)eidx;
        s = p[i];
        d = p[E + i];
    }
    g_src[i] = s;
    g_dst[i] = d;
    atomicAdd(&g_cnt[d], 1);
}

// ---------------------------------------------------------------------------
// Single-block chunked exclusive scan of g_cnt -> g_rowptr (+cursor).
// ---------------------------------------------------------------------------
__global__ void k_scan1b(int N, int E) {
    __shared__ int ssum[1024];
    int t = threadIdx.x;
    int chunk = (N + 1023) / 1024;
    int a = t * chunk;
    int b = min(N, a + chunk);
    int s = 0;
    for (int i = a; i < b; i++) s += g_cnt[i];
    ssum[t] = s;
    __syncthreads();
    for (int off = 1; off < 1024; off <<= 1) {
        int u = (t >= off) ? ssum[t - off] : 0;
        __syncthreads();
        ssum[t] += u;
        __syncthreads();
    }
    int run = ssum[t] - s;  // exclusive prefix of this chunk
    for (int i = a; i < b; i++) {
        g_rowptr[i] = run;
        g_cursor[i] = run;
        run += g_cnt[i];
    }
    if (t == 1023) g_rowptr[N] = E;
}

// Fill CSR: pos = cursor[dst]++ ; csr[pos] = src.
__global__ void k_csrfill(int E) {
    int i = blockIdx.x * blockDim.x + threadIdx.x;
    if (i >= E) return;
    int d = g_dst[i];
    int pos = atomicAdd(&g_cursor[d], 1);
    g_csr[pos] = g_src[i];
}

// ---------------------------------------------------------------------------
// Layer 1: warp per node, scalar gather of x over CSR + 32-wide transform.
// ---------------------------------------------------------------------------
__global__ void k_l1(const float* __restrict__ x, const float* __restrict__ W1l,
                     const float* __restrict__ b1, const float* __restrict__ W1r,
                     int N) {
    int lane = threadIdx.x & 31;
    int node = (blockIdx.x * blockDim.x + threadIdx.x) >> 5;
    if (node >= N) return;
    int s0 = g_rowptr[node], s1 = g_rowptr[node + 1];
    float a = 0.f;
    for (int j = s0 + lane; j < s1; j += 32) a += __ldg(&x[__ldg(&g_csr[j])]);
    #pragma unroll
    for (int off = 16; off > 0; off >>= 1) a += __shfl_xor_sync(0xffffffffu, a, off);
    float xv = __ldg(&x[node]);
    g_h1[node * 32 + lane] =
        lrelu(a * __ldg(&W1l[lane]) + xv * __ldg(&W1r[lane]) + __ldg(&b1[lane]));
}

// ---------------------------------------------------------------------------
// Layer 2: 4 nodes per warp. Sub-group (8 lanes) owns one node; lane's chunk
// q=lane&7 covers channels 4q..4q+3. Gather: one LDG.128 per edge per lane.
// GEMM: agg_k / hv_k broadcast via shfl within sub-group (static component).
// ---------------------------------------------------------------------------
__global__ void k_sage2g4(const float* __restrict__ Wl, const float* __restrict__ b,
                          const float* __restrict__ Wr, int N) {
    __shared__ float4 sWl4[256], sWr4[256];   // [k*8+q] = W[k][4q..4q+3]
    __shared__ float4 sb4[8];
    for (int i = threadIdx.x; i < 256; i += blockDim.x) {
        sWl4[i] = ((const float4*)Wl)[i];
        sWr4[i] = ((const float4*)Wr)[i];
    }
    if (threadIdx.x < 8) sb4[threadIdx.x] = ((const float4*)b)[threadIdx.x];
    __syncthreads();

    int lane = threadIdx.x & 31;
    int warp = (blockIdx.x * blockDim.x + threadIdx.x) >> 5;
    int sub = lane >> 3, q = lane & 7;
    int node = warp * 4 + sub;
    bool valid = (node < N);
    int nclamp = valid ? node : (N - 1);
    int s0 = g_rowptr[nclamp], s1 = g_rowptr[nclamp + 1];
    int deg = s1 - s0;

    const float4* h1v = (const float4*)g_h1;
    float4 acc = make_float4(0.f, 0.f, 0.f, 0.f);
    int t = 0;
    for (; t + 2 <= deg; t += 2) {
        int i0 = __ldg(&g_csr[s0 + t]);
        int i1 = __ldg(&g_csr[s0 + t + 1]);
        float4 v0 = __ldg(&h1v[i0 * 8 + q]);
        float4 v1 = __ldg(&h1v[i1 * 8 + q]);
        acc.x += v0.x + v1.x; acc.y += v0.y + v1.y;
        acc.z += v0.z + v1.z; acc.w += v0.w + v1.w;
    }
    if (t < deg) {
        int i0 = __ldg(&g_csr[s0 + t]);
        float4 v0 = __ldg(&h1v[i0 * 8 + q]);
        acc.x += v0.x; acc.y += v0.y; acc.z += v0.z; acc.w += v0.w;
    }
    float4 hv = __ldg(&h1v[nclamp * 8 + q]);

    float4 o = sb4[q];
    int base = sub << 3;
    #pragma unroll
    for (int k = 0; k < 32; k++) {
        int sl = base + (k >> 2);
        float ak, hk;
        switch (k & 3) {
            case 0: ak = __shfl_sync(0xffffffffu, acc.x, sl); hk = __shfl_sync(0xffffffffu, hv.x, sl); break;
            case 1: ak = __shfl_sync(0xffffffffu, acc.y, sl); hk = __shfl_sync(0xffffffffu, hv.y, sl); break;
            case 2: ak = __shfl_sync(0xffffffffu, acc.z, sl); hk = __shfl_sync(0xffffffffu, hv.z, sl); break;
            default: ak = __shfl_sync(0xffffffffu, acc.w, sl); hk = __shfl_sync(0xffffffffu, hv.w, sl); break;
        }
        float4 wl = sWl4[k * 8 + q];
        float4 wr = sWr4[k * 8 + q];
        o.x += ak * wl.x + hk * wr.x;
        o.y += ak * wl.y + hk * wr.y;
        o.z += ak * wl.z + hk * wr.z;
        o.w += ak * wl.w + hk * wr.w;
    }
    if (valid) ((float4*)g_h2)[node * 8 + q] = lrelu4(o);
}

// ---------------------------------------------------------------------------
// Layer 3 (mean aggr) + up-projection. Same 4-node/warp layout; the 32->128
// up-proj is done one node at a time with all 32 lanes (lane = 4 out chans).
// ---------------------------------------------------------------------------
__global__ void k_sage3g4(const float* __restrict__ W3l, const float* __restrict__ b3,
                          const float* __restrict__ W3r, const float* __restrict__ Wu,
                          const float* __restrict__ bu, int N) {
    __shared__ float4 sWl4[256], sWr4[256];
    __shared__ float4 sWu4[1024];   // [k*32+l] = Wu[k][4l..4l+3]
    __shared__ float4 sb4[8], sbu4[32];
    for (int i = threadIdx.x; i < 256; i += blockDim.x) {
        sWl4[i] = ((const float4*)W3l)[i];
        sWr4[i] = ((const float4*)W3r)[i];
    }
    for (int i = threadIdx.x; i < 1024; i += blockDim.x) sWu4[i] = ((const float4*)Wu)[i];
    if (threadIdx.x < 8)  sb4[threadIdx.x]  = ((const float4*)b3)[threadIdx.x];
    if (threadIdx.x < 32) sbu4[threadIdx.x] = ((const float4*)bu)[threadIdx.x];
    __syncthreads();

    int lane = threadIdx.x & 31;
    int warp = (blockIdx.x * blockDim.x + threadIdx.x) >> 5;
    int sub = lane >> 3, q = lane & 7;
    int node = warp * 4 + sub;
    bool valid = (node < N);
    int nclamp = valid ? node : (N - 1);
    int s0 = g_rowptr[nclamp], s1 = g_rowptr[nclamp + 1];
    int deg = s1 - s0;

    const float4* h2v = (const float4*)g_h2;
    float4 acc = make_float4(0.f, 0.f, 0.f, 0.f);
    int t = 0;
    for (; t + 2 <= deg; t += 2) {
        int i0 = __ldg(&g_csr[s0 + t]);
        int i1 = __ldg(&g_csr[s0 + t + 1]);
        float4 v0 = __ldg(&h2v[i0 * 8 + q]);
        float4 v1 = __ldg(&h2v[i1 * 8 + q]);
        acc.x += v0.x + v1.x; acc.y += v0.y + v1.y;
        acc.z += v0.z + v1.z; acc.w += v0.w + v1.w;
    }
    if (t < deg) {
        int i0 = __ldg(&g_csr[s0 + t]);
        float4 v0 = __ldg(&h2v[i0 * 8 + q]);
        acc.x += v0.x; acc.y += v0.y; acc.z += v0.z; acc.w += v0.w;
    }
    float inv = 1.0f / fmaxf((float)deg, 1.0f);
    acc.x *= inv; acc.y *= inv; acc.z *= inv; acc.w *= inv;
    float4 hv = __ldg(&h2v[nclamp * 8 + q]);

    float4 o = sb4[q];
    int base = sub << 3;
    #pragma unroll
    for (int k = 0; k < 32; k++) {
        int sl = base + (k >> 2);
        float ak, hk;
        switch (k & 3) {
            case 0: ak = __shfl_sync(0xffffffffu, acc.x, sl); hk = __shfl_sync(0xffffffffu, hv.x, sl); break;
            case 1: ak = __shfl_sync(0xffffffffu, acc.y, sl); hk = __shfl_sync(0xffffffffu, hv.y, sl); break;
            case 2: ak = __shfl_sync(0xffffffffu, acc.z, sl); hk = __shfl_sync(0xffffffffu, hv.z, sl); break;
            default: ak = __shfl_sync(0xffffffffu, acc.w, sl); hk = __shfl_sync(0xffffffffu, hv.w, sl); break;
        }
        float4 wl = sWl4[k * 8 + q];
        float4 wr = sWr4[k * 8 + q];
        o.x += ak * wl.x + hk * wr.x;
        o.y += ak * wl.y + hk * wr.y;
        o.z += ak * wl.z + hk * wr.z;
        o.w += ak * wl.w + hk * wr.w;
    }
    float4 h3 = lrelu4(o);   // chunk q of node `node`

    // Up-proj: one node at a time, all 32 lanes (lane covers out chans 4*lane..).
    #pragma unroll
    for (int nn = 0; nn < 3 + 1; nn++) {
        int tgt = warp * 4 + nn;
        float4 u = sbu4[lane];
        int nb = nn << 3;
        #pragma unroll
        for (int k = 0; k < 32; k++) {
            int sl = nb + (k >> 2);
            float hk;
            switch (k & 3) {
                case 0: hk = __shfl_sync(0xffffffffu, h3.x, sl); break;
                case 1: hk = __shfl_sync(0xffffffffu, h3.y, sl); break;
                case 2: hk = __shfl_sync(0xffffffffu, h3.z, sl); break;
                default: hk = __shfl_sync(0xffffffffu, h3.w, sl); break;
            }
            float4 w = sWu4[k * 32 + lane];
            u.x += hk * w.x; u.y += hk * w.y; u.z += hk * w.z; u.w += hk * w.w;
        }
        if (tgt < N) ((float4*)g_h4)[(size_t)tgt * 32 + lane] = lrelu4(u);
    }
}

// ---------------------------------------------------------------------------
// Per-graph start offsets from sorted batch array.
// ---------------------------------------------------------------------------
__global__ void k_starts(const void* __restrict__ batch, int N, int G) {
    int i = blockIdx.x * blockDim.x + threadIdx.x;
    if (i >= N) return;
    long long bi, bp;
    if (g_flags[1]) {
        const long long* p = (const long long*)batch;
        bi = p[i]; bp = (i == 0) ? -1LL : p[i - 1];
    } else {
        const int* p = (const int*)batch;
        bi = p[i]; bp = (i == 0) ? -1LL : p[i - 1];
    }
    if (bi != bp) for (long long g = bp + 1; g <= bi; g++) g_start[g] = i;
    if (i == N - 1) for (long long g = bi + 1; g <= G; g++) g_start[g] = N;
}

// ---------------------------------------------------------------------------
// Pooling partials: 8 blocks per graph, 128 threads (one per channel).
// ---------------------------------------------------------------------------
__global__ void k_pool(int G) {
    int g = blockIdx.x >> 3;
    int q = blockIdx.x & 7;
    int c = threadIdx.x;
    int s = g_start[g], e = g_start[g + 1];
    int len = e - s;
    int q0 = s + (len * q) / 8;
    int q1 = s + (len * (q + 1)) / 8;
    float sum = 0.f, mx = -INFINITY;
    for (int i = q0; i < q1; i++) {
        float v = g_h4[(size_t)i * 128 + c];
        sum += v;
        mx = fmaxf(mx, v);
    }
    g_part[(g * 8 + q) * 256 + c]       = sum;
    g_part[(g * 8 + q) * 256 + 128 + c] = mx;
}

// ---------------------------------------------------------------------------
// Head: combine partials -> z[384] -> lrelu(@Wf1+bf1) -> @Wf2+bf2.
// ---------------------------------------------------------------------------
__global__ void k_head(const float* __restrict__ Wf1, const float* __restrict__ bf1,
                       const float* __restrict__ Wf2, const float* __restrict__ bf2,
                       float* __restrict__ out, int G) {
    __shared__ float sz[384], sz2[128];
    int g = blockIdx.x;
    int c = threadIdx.x;
    float sum = 0.f, mx = -INFINITY;
    #pragma unroll
    for (int q = 0; q < 8; q++) {
        sum += g_part[(g * 8 + q) * 256 + c];
        mx = fmaxf(mx, g_part[(g * 8 + q) * 256 + 128 + c]);
    }
    float cnt = (float)(g_start[g + 1] - g_start[g]);
    sz[c]       = sum / fmaxf(cnt, 1.0f);
    sz[128 + c] = mx;
    sz[256 + c] = sum;
    __syncthreads();
    float acc = bf1[c];
    #pragma unroll 4
    for (int k = 0; k < 384; k++) acc += sz[k] * Wf1[k * 128 + c];
    sz2[c] = lrelu(acc);
    __syncthreads();
    if (c < 51) {
        float o = bf2[c];
        #pragma unroll 4
        for (int k = 0; k < 128; k++) o += sz2[k] * Wf2[k * 51 + c];
        out[g * 51 + c] = o;
    }
}

// ---------------------------------------------------------------------------
extern "C" void kernel_launch(void* const* d_in, const int* in_sizes, int n_in,
                              void* d_out, int out_size) {
    const float* x    = (const float*)d_in[0];
    const void*  eidx = d_in[1];
    const void*  batch= d_in[2];
    const float* W1l  = (const float*)d_in[3];
    const float* b1   = (const float*)d_in[4];
    const float* W1r  = (const float*)d_in[5];
    const float* W2l  = (const float*)d_in[6];
    const float* b2   = (const float*)d_in[7];
    const float* W2r  = (const float*)d_in[8];
    const float* W3l  = (const float*)d_in[9];
    const float* b3   = (const float*)d_in[10];
    const float* W3r  = (const float*)d_in[11];
    const float* Wu   = (const float*)d_in[12];
    const float* bu   = (const float*)d_in[13];
    const float* Wf1  = (const float*)d_in[14];
    const float* bf1  = (const float*)d_in[15];
    const float* Wf2  = (const float*)d_in[16];
    const float* bf2  = (const float*)d_in[17];
    float* out = (float*)d_out;

    int N = in_sizes[0];
    int E = in_sizes[1] / 2;
    int G = out_size / 51;

    int bbase = (N - 64) & ~1;
    int warp4_blocks = (N / 4 + 7) / 8;   // 8 warps/block, 4 nodes/warp

    k_init<<<(N + 255) / 256, 256>>>((const unsigned int*)eidx,
                                     (const unsigned int*)batch, bbase, N);
    k_convert_hist<<<(E + 255) / 256, 256>>>(eidx, E);
    k_scan1b<<<1, 1024>>>(N, E);
    k_csrfill<<<(E + 255) / 256, 256>>>(E);
    k_l1<<<(N + 7) / 8, 256>>>(x, W1l, b1, W1r, N);
    k_sage2g4<<<warp4_blocks, 256>>>(W2l, b2, W2r, N);
    k_sage3g4<<<warp4_blocks, 256>>>(W3l, b3, W3r, Wu, bu, N);
    k_starts<<<(N + 255) / 256, 256>>>(batch, N, G);
    k_pool<<<G * 8, 128>>>(G);
    k_head<<<G, 128>>>(Wf1, bf1, Wf2, bf2, out, G);
}

// round 6
// speedup vs baseline: 1.2409x; 1.2409x over previous
#include <cuda_runtime.h>
#include <cuda_bf16.h>
#include <math.h>

// ----------------------------------------------------------------------------
// Fully-fused persistent kernel: GraphSAGE (3 layers) + up-proj + tri-pooling
// + MLP head in ONE launch with software grid barriers.
// N=100000, E=1600000, G=256, H=32, UP=128, out 51.
// Grid fixed at 444 blocks x 256 threads, __launch_bounds__(256,3) guarantees
// full residency (148 SMs x 3 blocks) so the grid barrier cannot deadlock.
// ----------------------------------------------------------------------------

#define MAXN 100000
#define MAXE 1600000
#define MAXG 256
#define NBLK 444
#define NTHR 256

__device__ int   g_csr[MAXE];
__device__ int   g_src[MAXE];
__device__ int   g_dst[MAXE];
__device__ int   g_cnt[MAXN];
__device__ int   g_rowptr[MAXN + 1];
__device__ int   g_cursor[MAXN];
__device__ int   g_tsum[512];
__device__ int   g_toff[512];
__device__ float g_h1[MAXN * 32];
__device__ float g_h2[MAXN * 32];
__device__ float g_h4[(size_t)MAXN * 128];
__device__ int   g_start[MAXG + 1];
__device__ float g_part[MAXG * 8 * 256];
__device__ int   g_flags[2];
__device__ unsigned g_bar_count;   // zero-initialized, returns to 0 each barrier
__device__ unsigned g_bar_gen;

union SmemU {
    int iscan[1024];
    struct { float wl[1024], wr[1024], b[32]; } s2;
    struct { float wl[1024], wr[1024], wu[4096], b[32], bu[128]; } s3;
    struct { float sz[384], sz2[128]; } hd;
};

__device__ __forceinline__ float lrelu(float v) { return v > 0.f ? v : 0.01f * v; }

// Release/acquire software grid barrier (the CG grid.sync protocol).
__device__ __forceinline__ void grid_barrier() {
    __syncthreads();
    if (threadIdx.x == 0) {
        unsigned gen;
        asm volatile("ld.acquire.gpu.u32 %0, [%1];"
                     : "=r"(gen) : "l"(&g_bar_gen) : "memory");
        unsigned prev;
        asm volatile("atom.acq_rel.gpu.add.u32 %0, [%1], 1;"
                     : "=r"(prev) : "l"(&g_bar_count) : "memory");
        if (prev == (unsigned)(gridDim.x - 1)) {
            asm volatile("st.relaxed.gpu.u32 [%0], %1;"
                         :: "l"(&g_bar_count), "r"(0u) : "memory");
            unsigned dummy;
            asm volatile("atom.release.gpu.add.u32 %0, [%1], 1;"
                         : "=r"(dummy) : "l"(&g_bar_gen) : "memory");
        } else {
            unsigned cur;
            do {
                __nanosleep(64);
                asm volatile("ld.acquire.gpu.u32 %0, [%1];"
                             : "=r"(cur) : "l"(&g_bar_gen) : "memory");
            } while (cur == gen);
        }
    }
    __syncthreads();
}

// Warp-cooperative 32-channel gather-sum over CSR edges (round-4 proven body).
__device__ __forceinline__ float gather32(const float* __restrict__ h,
                                          int s0, int s1, int lane) {
    float a0 = 0.f, a1 = 0.f, a2 = 0.f, a3 = 0.f;
    for (int base = s0; base < s1; base += 32) {
        int e = base + lane;
        int sidx = (e < s1) ? __ldg(&g_csr[e]) : 0;
        int cnt = min(32, s1 - base);
        int k = 0;
        for (; k + 4 <= cnt; k += 4) {
            int i0 = __shfl_sync(0xffffffffu, sidx, k);
            int i1 = __shfl_sync(0xffffffffu, sidx, k + 1);
            int i2 = __shfl_sync(0xffffffffu, sidx, k + 2);
            int i3 = __shfl_sync(0xffffffffu, sidx, k + 3);
            a0 += __ldg(&h[i0 * 32 + lane]);
            a1 += __ldg(&h[i1 * 32 + lane]);
            a2 += __ldg(&h[i2 * 32 + lane]);
            a3 += __ldg(&h[i3 * 32 + lane]);
        }
        for (; k < cnt; k++) {
            int ik = __shfl_sync(0xffffffffu, sidx, k);
            a0 += __ldg(&h[ik * 32 + lane]);
        }
    }
    return (a0 + a1) + (a2 + a3);
}

__global__ __launch_bounds__(NTHR, 3)
void k_all(const float* __restrict__ x, const void* __restrict__ eidx,
           const void* __restrict__ batch,
           const float* __restrict__ W1l, const float* __restrict__ b1,
           const float* __restrict__ W1r,
           const float* __restrict__ W2l, const float* __restrict__ b2,
           const float* __restrict__ W2r,
           const float* __restrict__ W3l, const float* __restrict__ b3,
           const float* __restrict__ W3r,
           const float* __restrict__ Wu, const float* __restrict__ bu,
           const float* __restrict__ Wf1, const float* __restrict__ bf1,
           const float* __restrict__ Wf2, const float* __restrict__ bf2,
           float* __restrict__ out, int N, int E, int G, int bbase)
{
    __shared__ SmemU u;
    const int tid = threadIdx.x;
    const int gid = blockIdx.x * NTHR + tid;
    const int gsz = NBLK * NTHR;
    const int lane = tid & 31;
    const int wblk = tid >> 5;
    const int gwarp = blockIdx.x * (NTHR / 32) + wblk;
    const int nwarp = NBLK * (NTHR / 32);

    // ---- P0: zero histogram + dtype detect ----
    for (int i = gid; i < N; i += gsz) g_cnt[i] = 0;
    if (blockIdx.x == 0 && tid < 64) {
        const unsigned* ew = (const unsigned*)eidx;
        const unsigned* bw = (const unsigned*)batch;
        if (tid < 32) {
            unsigned nz = __ballot_sync(0xffffffffu, ew[2 * lane + 1] != 0u);
            if (lane == 0) g_flags[0] = (nz == 0u);
        } else {
            unsigned nz = __ballot_sync(0xffffffffu, bw[bbase + 2 * lane + 1] != 0u);
            if (lane == 0) g_flags[1] = (nz == 0u);
        }
    }
    grid_barrier();

    // ---- P1: convert edges to int32 + in-degree histogram ----
    if (g_flags[0]) {
        const long long* p = (const long long*)eidx;
        for (int i = gid; i < E; i += gsz) {
            int s = (int)p[i], d = (int)p[(size_t)E + i];
            g_src[i] = s; g_dst[i] = d;
            atomicAdd(&g_cnt[d], 1);
        }
    } else {
        const int* p = (const int*)eidx;
        for (int i = gid; i < E; i += gsz) {
            int s = p[i], d = p[E + i];
            g_src[i] = s; g_dst[i] = d;
            atomicAdd(&g_cnt[d], 1);
        }
    }
    grid_barrier();

    // ---- P2a: per-tile (256-node) sums ----
    const int T = (N + 255) / 256;
    for (int t = blockIdx.x; t < T; t += NBLK) {
        int i = t * 256 + tid;
        int v = (i < N) ? g_cnt[i] : 0;
        int s = v;
        #pragma unroll
        for (int off = 16; off; off >>= 1) s += __shfl_xor_sync(0xffffffffu, s, off);
        if (lane == 0) u.iscan[wblk] = s;
        __syncthreads();
        if (tid == 0) {
            int tot = 0;
            #pragma unroll
            for (int w = 0; w < NTHR / 32; w++) tot += u.iscan[w];
            g_tsum[t] = tot;
        }
        __syncthreads();
    }
    grid_barrier();

    // ---- P2b: block 0 scans tile sums ----
    if (blockIdx.x == 0) {
        for (int t = tid; t < T; t += NTHR) u.iscan[t] = g_tsum[t];
        __syncthreads();
        if (tid == 0) {
            int run = 0;
            for (int t = 0; t < T; t++) { g_toff[t] = run; run += u.iscan[t]; }
            g_rowptr[N] = E;
        }
    }
    grid_barrier();

    // ---- P2c: per-tile exclusive scan -> rowptr, cursor ----
    for (int t = blockIdx.x; t < T; t += NBLK) {
        int i = t * 256 + tid;
        int v = (i < N) ? g_cnt[i] : 0;
        u.iscan[tid] = v;
        __syncthreads();
        for (int off = 1; off < 256; off <<= 1) {
            int add = (tid >= off) ? u.iscan[tid - off] : 0;
            __syncthreads();
            u.iscan[tid] += add;
            __syncthreads();
        }
        int ex = u.iscan[tid] - v + g_toff[t];
        if (i < N) { g_rowptr[i] = ex; g_cursor[i] = ex; }
        __syncthreads();
    }
    grid_barrier();

    // ---- P3: CSR fill ----
    for (int i = gid; i < E; i += gsz) {
        int d = g_dst[i];
        int pos = atomicAdd(&g_cursor[d], 1);
        g_csr[pos] = g_src[i];
    }
    grid_barrier();

    // ---- P4: layer 1 (scalar gather + 32-wide transform), warp per node ----
    for (int node = gwarp; node < N; node += nwarp) {
        int s0 = g_rowptr[node], s1 = g_rowptr[node + 1];
        float a = 0.f;
        for (int j = s0 + lane; j < s1; j += 32) a += __ldg(&x[__ldg(&g_csr[j])]);
        #pragma unroll
        for (int off = 16; off; off >>= 1) a += __shfl_xor_sync(0xffffffffu, a, off);
        float xv = __ldg(&x[node]);
        g_h1[node * 32 + lane] =
            lrelu(a * __ldg(&W1l[lane]) + xv * __ldg(&W1r[lane]) + __ldg(&b1[lane]));
    }
    grid_barrier();

    // ---- P5: layer 2 (gather + shuffle GEMM), warp per node ----
    for (int i = tid; i < 1024; i += NTHR) { u.s2.wl[i] = W2l[i]; u.s2.wr[i] = W2r[i]; }
    if (tid < 32) u.s2.b[tid] = b2[tid];
    __syncthreads();
    for (int node = gwarp; node < N; node += nwarp) {
        int s0 = g_rowptr[node], s1 = g_rowptr[node + 1];
        float agg = gather32(g_h1, s0, s1, lane);
        float hv = g_h1[node * 32 + lane];
        float acc = u.s2.b[lane];
        #pragma unroll
        for (int k = 0; k < 32; k++) {
            acc += __shfl_sync(0xffffffffu, agg, k) * u.s2.wl[k * 32 + lane]
                 + __shfl_sync(0xffffffffu, hv, k)  * u.s2.wr[k * 32 + lane];
        }
        g_h2[node * 32 + lane] = lrelu(acc);
    }
    grid_barrier();

    // ---- P6: graph starts (independent)  +  layer 3 (mean) + up-proj ----
    for (int i = gid; i < N; i += gsz) {
        long long bi, bp;
        if (g_flags[1]) {
            const long long* p = (const long long*)batch;
            bi = p[i]; bp = (i == 0) ? -1LL : p[i - 1];
        } else {
            const int* p = (const int*)batch;
            bi = p[i]; bp = (i == 0) ? -1LL : p[i - 1];
        }
        if (bi != bp) for (long long g = bp + 1; g <= bi; g++) g_start[g] = i;
        if (i == N - 1) for (long long g = bi + 1; g <= G; g++) g_start[g] = N;
    }
    for (int i = tid; i < 1024; i += NTHR) { u.s3.wl[i] = W3l[i]; u.s3.wr[i] = W3r[i]; }
    for (int i = tid; i < 4096; i += NTHR) u.s3.wu[i] = Wu[i];
    if (tid < 32)  u.s3.b[tid]  = b3[tid];
    if (tid < 128) u.s3.bu[tid] = bu[tid];
    __syncthreads();
    for (int node = gwarp; node < N; node += nwarp) {
        int s0 = g_rowptr[node], s1 = g_rowptr[node + 1];
        float agg = gather32(g_h2, s0, s1, lane);
        agg *= 1.0f / fmaxf((float)(s1 - s0), 1.0f);
        float hv = g_h2[node * 32 + lane];
        float acc = u.s3.b[lane];
        #pragma unroll
        for (int k = 0; k < 32; k++) {
            acc += __shfl_sync(0xffffffffu, agg, k) * u.s3.wl[k * 32 + lane]
                 + __shfl_sync(0xffffffffu, hv, k)  * u.s3.wr[k * 32 + lane];
        }
        float h3 = lrelu(acc);
        float4 o = *(const float4*)(u.s3.bu + lane * 4);
        #pragma unroll
        for (int k = 0; k < 32; k++) {
            float hk = __shfl_sync(0xffffffffu, h3, k);
            float4 w = *(const float4*)(u.s3.wu + k * 128 + lane * 4);
            o.x += hk * w.x; o.y += hk * w.y; o.z += hk * w.z; o.w += hk * w.w;
        }
        o.x = lrelu(o.x); o.y = lrelu(o.y); o.z = lrelu(o.z); o.w = lrelu(o.w);
        *(float4*)(g_h4 + (size_t)node * 128 + lane * 4) = o;
    }
    grid_barrier();

    // ---- P7: pooling partials (8 octants per graph) ----
    for (int task = blockIdx.x; task < G * 8; task += NBLK) {
        if (tid < 128) {
            int g = task >> 3, q = task & 7;
            int s = g_start[g], e = g_start[g + 1];
            int len = e - s;
            int q0 = s + (len * q) / 8;
            int q1 = s + (len * (q + 1)) / 8;
            float sum = 0.f, mx = -INFINITY;
            for (int i = q0; i < q1; i++) {
                float v = g_h4[(size_t)i * 128 + tid];
                sum += v;
                mx = fmaxf(mx, v);
            }
            g_part[(g * 8 + q) * 256 + tid]       = sum;
            g_part[(g * 8 + q) * 256 + 128 + tid] = mx;
        }
    }
    grid_barrier();

    // ---- P8: head (block per graph) ----
    for (int g = blockIdx.x; g < G; g += NBLK) {
        if (tid < 128) {
            float sum = 0.f, mx = -INFINITY;
            #pragma unroll
            for (int q = 0; q < 8; q++) {
                sum += g_part[(g * 8 + q) * 256 + tid];
                mx = fmaxf(mx, g_part[(g * 8 + q) * 256 + 128 + tid]);
            }
            float cnt = (float)(g_start[g + 1] - g_start[g]);
            u.hd.sz[tid]       = sum / fmaxf(cnt, 1.0f);
            u.hd.sz[128 + tid] = mx;
            u.hd.sz[256 + tid] = sum;
        }
        __syncthreads();
        if (tid < 128) {
            float acc = bf1[tid];
            #pragma unroll 4
            for (int k = 0; k < 384; k++) acc += u.hd.sz[k] * Wf1[k * 128 + tid];
            u.hd.sz2[tid] = lrelu(acc);
        }
        __syncthreads();
        if (tid < 51) {
            float o = bf2[tid];
            #pragma unroll 4
            for (int k = 0; k < 128; k++) o += u.hd.sz2[k] * Wf2[k * 51 + tid];
            out[g * 51 + tid] = o;
        }
        __syncthreads();
    }
}

// ---------------------------------------------------------------------------
extern "C" void kernel_launch(void* const* d_in, const int* in_sizes, int n_in,
                              void* d_out, int out_size) {
    const float* x    = (const float*)d_in[0];
    const void*  eidx = d_in[1];
    const void*  batch= d_in[2];

    int N = in_sizes[0];
    int E = in_sizes[1] / 2;
    int G = out_size / 51;
    int bbase = (N - 64) & ~1;

    k_all<<<NBLK, NTHR>>>(x, eidx, batch,
                          (const float*)d_in[3],  (const float*)d_in[4],
                          (const float*)d_in[5],
                          (const float*)d_in[6],  (const float*)d_in[7],
                          (const float*)d_in[8],
                          (const float*)d_in[9],  (const float*)d_in[10],
                          (const float*)d_in[11],
                          (const float*)d_in[12], (const float*)d_in[13],
                          (const float*)d_in[14], (const float*)d_in[15],
                          (const float*)d_in[16], (const float*)d_in[17],
                          (float*)d_out, N, E, G, bbase);
}